// round 11
// baseline (speedup 1.0000x reference)
#include <cuda_runtime.h>
#include <cuda_fp16.h>
#include <cstdint>

// ---------------- problem sizes ----------------
#define SZ_M 8192   // 4 * 2048 rows of x
#define SZ_N 4096   // out features
#define SZ_K 4096   // in features

// ---------------- GEMM tiling ----------------
#define BM 128
#define BN 256                 // 2 groups x 128 cols
#define BK 64                  // halves per stage = 128B rows (one SW128 plane)
#define NSTAGE 3
#define KIT (SZ_K / BK)        // 64 k-iterations per tile
#define NTHREADS 256           // 2 groups x 128 threads (4 warps each)

#define NTILE_N (SZ_N / BN)    // 16
#define NTILE_M (SZ_M / BM)    // 64
#define NTILES  (NTILE_N * NTILE_M)   // 1024
#define GRID    148            // persistent: one CTA per SM

// per-group per-stage: A copy 128x128B (16K) + B half 128x128B (16K)
#define GROUP_A_BYTES (BM * 128)               // 16384
#define GROUP_B_BYTES (128 * 128)              // 16384
#define GROUP_BYTES   (GROUP_A_BYTES + GROUP_B_BYTES)   // 32768
#define STAGE_BYTES   (2 * GROUP_BYTES)                 // 65536
#define SMEM_TOTAL    (NSTAGE * STAGE_BYTES)            // 196608

static_assert(SZ_M % BM == 0 && SZ_N % BN == 0 && SZ_K % BK == 0, "tiling");

// ---------------- scratch (no cudaMalloc allowed) ----------------
__device__ __align__(16) __half g_wh[(size_t)SZ_N * SZ_K];   // 32 MB: W in fp16

// ---------------- helpers ----------------
static __device__ __forceinline__ uint32_t smem_u32(const void* p) {
    uint32_t r;
    asm("{ .reg .u64 t; cvta.to.shared.u64 t, %1; cvt.u32.u64 %0, t; }"
        : "=r"(r) : "l"(p));
    return r;
}

static __device__ __forceinline__ void cp16(uint32_t dst, const void* src) {
    asm volatile("cp.async.cg.shared.global [%0], [%1], 16;"
                 :: "r"(dst), "l"(src) : "memory");
}

static __device__ __forceinline__ uint32_t sw128(uint32_t off) {
    return off ^ ((off >> 3) & 0x70);
}

static __device__ __forceinline__ void ldm_x4(uint32_t addr,
    uint32_t& r0, uint32_t& r1, uint32_t& r2, uint32_t& r3) {
    asm volatile("ldmatrix.sync.aligned.m8n8.x4.shared.b16 {%0,%1,%2,%3}, [%4];"
                 : "=r"(r0), "=r"(r1), "=r"(r2), "=r"(r3) : "r"(addr));
}

static __device__ __forceinline__ void mma16816(
    float& d0, float& d1, float& d2, float& d3,
    uint32_t a0, uint32_t a1, uint32_t a2, uint32_t a3,
    uint32_t b0, uint32_t b1) {
    asm volatile(
        "mma.sync.aligned.m16n8k16.row.col.f32.f16.f16.f32 "
        "{%0,%1,%2,%3}, {%4,%5,%6,%7}, {%8,%9}, {%0,%1,%2,%3};"
        : "+f"(d0), "+f"(d1), "+f"(d2), "+f"(d3)
        : "r"(a0), "r"(a1), "r"(a2), "r"(a3), "r"(b0), "r"(b1));
}

// group-scoped named barrier (128 threads)
static __device__ __forceinline__ void group_bar(int g) {
    asm volatile("bar.sync %0, 128;" :: "r"(g + 1) : "memory");
}

// ---------------- W convert kernel (x converts inline in the GEMM) ----------------
#define WC ((size_t)SZ_N * SZ_K / 4)

__global__ void __launch_bounds__(256) cvt_w_kernel(const int* __restrict__ q) {
    size_t j = (size_t)blockIdx.x * blockDim.x + threadIdx.x;  // one per 4 ints
    int4 v = reinterpret_cast<const int4*>(q)[j];
    __half2 h0 = __halves2half2(__int2half_rn(v.x), __int2half_rn(v.y));
    __half2 h1 = __halves2half2(__int2half_rn(v.z), __int2half_rn(v.w));
    uint2 r;
    r.x = *reinterpret_cast<unsigned*>(&h0);
    r.y = *reinterpret_cast<unsigned*>(&h1);
    reinterpret_cast<uint2*>(g_wh)[j] = r;
}

// ---------------- per-group stage loader (128 threads of group g) ----------------
// A: LDG fp32 from x, convert to fp16 in-register, STS (swizzled).
// B: cp.async from pre-converted g_wh.
static __device__ __forceinline__ void load_stage(
    char* smem, uint32_t sb, int s, int m0, int n0, int kt, int g, int gtid,
    const float* __restrict__ gx)
{
    const uint32_t boff = (uint32_t)s * STAGE_BYTES + (uint32_t)g * GROUP_BYTES;
    const int kh = kt * BK;

    // A: own copy of the full 128-row A tile; 8 chunks of 16B fp16 per thread,
    // each sourced from 32B of fp32 (2x LDG.128) and converted inline.
    #pragma unroll
    for (int i = 0; i < (BM * 8) / 128; i++) {
        int c = gtid + i * 128;
        int row = c >> 3, seg = c & 7;
        const float4* src = reinterpret_cast<const float4*>(
            gx + (size_t)(m0 + row) * SZ_K + kh + seg * 8);
        float4 v0 = __ldg(src);
        float4 v1 = __ldg(src + 1);
        __half2 h0 = __floats2half2_rn(v0.x, v0.y);
        __half2 h1 = __floats2half2_rn(v0.z, v0.w);
        __half2 h2 = __floats2half2_rn(v1.x, v1.y);
        __half2 h3 = __floats2half2_rn(v1.z, v1.w);
        uint4 pk;
        pk.x = *reinterpret_cast<unsigned*>(&h0);
        pk.y = *reinterpret_cast<unsigned*>(&h1);
        pk.z = *reinterpret_cast<unsigned*>(&h2);
        pk.w = *reinterpret_cast<unsigned*>(&h3);
        uint32_t off = (uint32_t)row * 128 + (uint32_t)seg * 16;
        *reinterpret_cast<uint4*>(smem + boff + sw128(off)) = pk;
    }
    // B half: group's 128 columns (8 chunks/thread) via cp.async
    const uint32_t bbase = sb + boff + GROUP_A_BYTES;
    const int bn0 = n0 + g * 128;
    #pragma unroll
    for (int i = 0; i < (128 * 8) / 128; i++) {
        int c = gtid + i * 128;
        int row = c >> 3, seg = c & 7;
        uint32_t off = (uint32_t)row * 128 + (uint32_t)seg * 16;
        cp16(bbase + sw128(off), g_wh + (size_t)(bn0 + row) * SZ_K + kh + seg * 8);
    }
}

// ---------------- persistent GEMM kernel ----------------
// R9 chassis: 148 persistent CTAs, 2 decorrelated 128-thread groups with named
// barriers, cp.async pipeline linearized across tile boundaries. NEW: A tiles
// are converted fp32->fp16 inline in the loader (no pre-pass for x).
__global__ void __launch_bounds__(NTHREADS, 1)
gemm_hmma_kernel(const float* __restrict__ gx,
                 const float* __restrict__ wscale,
                 const float* __restrict__ bias,
                 float* __restrict__ out)
{
    extern __shared__ char smem[];
    const uint32_t sb = smem_u32(smem);
    const int tid  = threadIdx.x;
    const int wid  = tid >> 5;
    const int lane = tid & 31;
    const int g    = wid >> 2;        // group 0/1
    const int w    = wid & 3;
    const int wm   = w & 1;
    const int wn   = w >> 1;
    const int gtid = tid & 127;
    const int bid  = blockIdx.x;

    const int ntiles = (NTILES - 1 - bid) / GRID + 1;
    const int GJ = ntiles * KIT;

    const int l7   = lane & 7;
    const int hi8  = (lane >> 3) & 1;
    const int hi16 = lane >> 4;

    const int arow_base = wm * 64 + hi8 * 8 + l7;
    const int akb_base  = hi16 * 16;
    const int brow_base = wn * 64 + hi16 * 8 + l7;
    const int bkb_base  = hi8 * 16;

    float d[4][8][4];
    #pragma unroll
    for (int i = 0; i < 4; i++)
        #pragma unroll
        for (int j = 0; j < 8; j++)
            #pragma unroll
            for (int c = 0; c < 4; c++) d[i][j][c] = 0.0f;

    auto load_j = [&](int j, int s) {
        const int ti = j >> 6;            // KIT = 64
        const int kt = j & 63;
        const int t  = bid + GRID * ti;
        const int n0 = (t & (NTILE_N - 1)) * BN;
        const int m0 = (t >> 4) * BM;
        load_stage(smem, sb, s, m0, n0, kt, g, gtid, gx);
    };

    load_j(0, 0);
    asm volatile("cp.async.commit_group;" ::: "memory");
    load_j(1, 1);
    asm volatile("cp.async.commit_group;" ::: "memory");

    int s0 = 0;   // stage of j
    int s2 = 2;   // stage of j+2

    #pragma unroll 1
    for (int j = 0; j < GJ; j++) {
        if (j + 2 < GJ)
            asm volatile("cp.async.wait_group 1;" ::: "memory");
        else
            asm volatile("cp.async.wait_group 0;" ::: "memory");
        group_bar(g);   // B cp.async landed (this thread) + all group STS drained

        if (j + 2 < GJ) {
            load_j(j + 2, s2);
            asm volatile("cp.async.commit_group;" ::: "memory");
        }

        const uint32_t abase = sb + (uint32_t)s0 * STAGE_BYTES + (uint32_t)g * GROUP_BYTES;
        const uint32_t bbase = abase + GROUP_A_BYTES;

        #pragma unroll
        for (int ks = 0; ks < BK / 16; ks++) {
            uint32_t a[4][4];
            #pragma unroll
            for (int mt = 0; mt < 4; mt++) {
                uint32_t off = (uint32_t)(arow_base + mt * 16) * 128
                             + (uint32_t)(ks * 32 + akb_base);
                ldm_x4(abase + sw128(off), a[mt][0], a[mt][1], a[mt][2], a[mt][3]);
            }
            uint32_t bfr[8][2];
            #pragma unroll
            for (int np = 0; np < 4; np++) {
                uint32_t off = (uint32_t)(brow_base + np * 16) * 128
                             + (uint32_t)(ks * 32 + bkb_base);
                uint32_t r0, r1, r2, r3;
                ldm_x4(bbase + sw128(off), r0, r1, r2, r3);
                bfr[np * 2 + 0][0] = r0; bfr[np * 2 + 0][1] = r1;
                bfr[np * 2 + 1][0] = r2; bfr[np * 2 + 1][1] = r3;
            }
            #pragma unroll
            for (int mt = 0; mt < 4; mt++)
                #pragma unroll
                for (int nt = 0; nt < 8; nt++)
                    mma16816(d[mt][nt][0], d[mt][nt][1], d[mt][nt][2], d[mt][nt][3],
                             a[mt][0], a[mt][1], a[mt][2], a[mt][3],
                             bfr[nt][0], bfr[nt][1]);
        }

        s0 = (s0 == 2) ? 0 : s0 + 1;
        s2 = (s2 == 2) ? 0 : s2 + 1;

        // ---------------- tile epilogue ----------------
        if ((j & 63) == 63) {
            const int t  = bid + GRID * (j >> 6);
            const int n0 = (t & (NTILE_N - 1)) * BN;
            const int m0 = (t >> 4) * BM;
            const int crow = m0 + wm * 64 + (lane >> 2);
            const int ccol = n0 + g * 128 + wn * 64 + (lane & 3) * 2;

            #pragma unroll
            for (int mt = 0; mt < 4; mt++) {
                #pragma unroll
                for (int nt = 0; nt < 8; nt++) {
                    const float s0f = __ldg(wscale + ccol + nt * 8);
                    const float s1f = __ldg(wscale + ccol + nt * 8 + 1);
                    const float b0f = __ldg(bias   + ccol + nt * 8);
                    const float b1f = __ldg(bias   + ccol + nt * 8 + 1);
                    float2 v0, v1;
                    v0.x = fmaf(d[mt][nt][0], s0f, b0f);
                    v0.y = fmaf(d[mt][nt][1], s1f, b1f);
                    v1.x = fmaf(d[mt][nt][2], s0f, b0f);
                    v1.y = fmaf(d[mt][nt][3], s1f, b1f);
                    size_t r0 = (size_t)(crow + mt * 16) * SZ_N + ccol + nt * 8;
                    size_t r1 = r0 + 8 * SZ_N;
                    *reinterpret_cast<float2*>(out + r0) = v0;
                    *reinterpret_cast<float2*>(out + r1) = v1;
                    d[mt][nt][0] = 0.0f; d[mt][nt][1] = 0.0f;
                    d[mt][nt][2] = 0.0f; d[mt][nt][3] = 0.0f;
                }
            }
        }
    }
}

// ---------------- launch ----------------
extern "C" void kernel_launch(void* const* d_in, const int* in_sizes, int n_in,
                              void* d_out, int out_size)
{
    const float* x  = (const float*)d_in[0];   // [4,2048,4096] fp32
    const int*   qw = (const int*)  d_in[1];   // [4096,4096] int32 in [-8,7]
    const float* ws = (const float*)d_in[2];   // [4096]
    const float* bs = (const float*)d_in[3];   // [4096]
    float* out = (float*)d_out;                // [4,2048,4096] fp32

    cudaFuncSetAttribute(gemm_hmma_kernel,
                         cudaFuncAttributeMaxDynamicSharedMemorySize, SMEM_TOTAL);

    cvt_w_kernel<<<(unsigned)(WC / 256), 256>>>(qw);

    gemm_hmma_kernel<<<GRID, NTHREADS, SMEM_TOTAL>>>(x, ws, bs, out);
}

// round 12
// speedup vs baseline: 1.9820x; 1.9820x over previous
#include <cuda_runtime.h>
#include <cuda_fp16.h>
#include <cstdint>

// ---------------- problem sizes ----------------
#define SZ_M 8192   // 4 * 2048 rows of x
#define SZ_N 4096   // out features
#define SZ_K 4096   // in features

// ---------------- GEMM tiling ----------------
#define BM 128
#define BN 256                 // 2 groups x 128 cols
#define BK 64                  // halves per stage = 128B rows (one SW128 plane)
#define NSTAGE 3
#define KIT (SZ_K / BK)        // 64 k-iterations per tile
#define NTHREADS 256           // 2 groups x 128 threads (4 warps each)

#define NTILE_N (SZ_N / BN)    // 16
#define NTILE_M (SZ_M / BM)    // 64
#define NTILES  (NTILE_N * NTILE_M)   // 1024
#define GRID    148            // persistent: one CTA per SM

// per-group per-stage: A copy 128x128B (16K) + B half 128x128B (16K)
#define GROUP_A_BYTES (BM * 128)               // 16384
#define GROUP_B_BYTES (128 * 128)              // 16384
#define GROUP_BYTES   (GROUP_A_BYTES + GROUP_B_BYTES)   // 32768
#define STAGE_BYTES   (2 * GROUP_BYTES)                 // 65536
#define SMEM_TOTAL    (NSTAGE * STAGE_BYTES)            // 196608

static_assert(SZ_M % BM == 0 && SZ_N % BN == 0 && SZ_K % BK == 0, "tiling");

// ---------------- scratch (no cudaMalloc allowed) ----------------
__device__ __align__(16) __half g_xh[(size_t)SZ_M * SZ_K];   // 64 MB
__device__ __align__(16) __half g_wh[(size_t)SZ_N * SZ_K];   // 32 MB

// ---------------- helpers ----------------
static __device__ __forceinline__ uint32_t smem_u32(const void* p) {
    uint32_t r;
    asm("{ .reg .u64 t; cvta.to.shared.u64 t, %1; cvt.u32.u64 %0, t; }"
        : "=r"(r) : "l"(p));
    return r;
}

static __device__ __forceinline__ void cp16(uint32_t dst, const void* src) {
    asm volatile("cp.async.cg.shared.global [%0], [%1], 16;"
                 :: "r"(dst), "l"(src) : "memory");
}

static __device__ __forceinline__ uint32_t sw128(uint32_t off) {
    return off ^ ((off >> 3) & 0x70);
}

static __device__ __forceinline__ void ldm_x4(uint32_t addr,
    uint32_t& r0, uint32_t& r1, uint32_t& r2, uint32_t& r3) {
    asm volatile("ldmatrix.sync.aligned.m8n8.x4.shared.b16 {%0,%1,%2,%3}, [%4];"
                 : "=r"(r0), "=r"(r1), "=r"(r2), "=r"(r3) : "r"(addr));
}

static __device__ __forceinline__ void mma16816(
    float& d0, float& d1, float& d2, float& d3,
    uint32_t a0, uint32_t a1, uint32_t a2, uint32_t a3,
    uint32_t b0, uint32_t b1) {
    asm volatile(
        "mma.sync.aligned.m16n8k16.row.col.f32.f16.f16.f32 "
        "{%0,%1,%2,%3}, {%4,%5,%6,%7}, {%8,%9}, {%0,%1,%2,%3};"
        : "+f"(d0), "+f"(d1), "+f"(d2), "+f"(d3)
        : "r"(a0), "r"(a1), "r"(a2), "r"(a3), "r"(b0), "r"(b1));
}

// group-scoped named barrier (128 threads)
static __device__ __forceinline__ void group_bar(int g) {
    asm volatile("bar.sync %0, 128;" :: "r"(g + 1) : "memory");
}

// ---------------- fused convert kernel ----------------
#define XC ((size_t)SZ_M * SZ_K / 4)
#define WC ((size_t)SZ_N * SZ_K / 4)

__global__ void __launch_bounds__(256) cvt_all_kernel(
    const float* __restrict__ x, const int* __restrict__ q)
{
    size_t i = (size_t)blockIdx.x * blockDim.x + threadIdx.x;
    if (i < XC) {
        float4 v = reinterpret_cast<const float4*>(x)[i];
        __half2 h0 = __floats2half2_rn(v.x, v.y);
        __half2 h1 = __floats2half2_rn(v.z, v.w);
        uint2 r;
        r.x = *reinterpret_cast<unsigned*>(&h0);
        r.y = *reinterpret_cast<unsigned*>(&h1);
        reinterpret_cast<uint2*>(g_xh)[i] = r;
    } else {
        size_t j = i - XC;
        int4 v = reinterpret_cast<const int4*>(q)[j];
        __half2 h0 = __halves2half2(__int2half_rn(v.x), __int2half_rn(v.y));
        __half2 h1 = __halves2half2(__int2half_rn(v.z), __int2half_rn(v.w));
        uint2 r;
        r.x = *reinterpret_cast<unsigned*>(&h0);
        r.y = *reinterpret_cast<unsigned*>(&h1);
        reinterpret_cast<uint2*>(g_wh)[j] = r;
    }
}

// ---------------- per-group stage loader (128 threads of group g) ----------------
static __device__ __forceinline__ void load_stage(
    uint32_t sb, int s, int m0, int n0, int kt, int g, int gtid)
{
    const uint32_t base = sb + (uint32_t)s * STAGE_BYTES + (uint32_t)g * GROUP_BYTES;
    const int kh = kt * BK;

    // A: own copy of the full 128-row A tile (8 chunks/thread)
    #pragma unroll
    for (int i = 0; i < (BM * 8) / 128; i++) {
        int c = gtid + i * 128;
        int row = c >> 3, seg = c & 7;
        uint32_t off = (uint32_t)row * 128 + (uint32_t)seg * 16;
        cp16(base + sw128(off), g_xh + (size_t)(m0 + row) * SZ_K + kh + seg * 8);
    }
    // B half: group's 128 columns (8 chunks/thread)
    const uint32_t bbase = base + GROUP_A_BYTES;
    const int bn0 = n0 + g * 128;
    #pragma unroll
    for (int i = 0; i < (128 * 8) / 128; i++) {
        int c = gtid + i * 128;
        int row = c >> 3, seg = c & 7;
        uint32_t off = (uint32_t)row * 128 + (uint32_t)seg * 16;
        cp16(bbase + sw128(off), g_wh + (size_t)(bn0 + row) * SZ_K + kh + seg * 8);
    }
}

// ---------------- persistent GEMM kernel ----------------
// R9 chassis: 148 persistent CTAs, 2 decorrelated 128-thread groups with named
// barriers, cp.async pipeline linearized across tile boundaries.
// Trims: incremental load-coordinate tracking (no per-iter div/mod chain),
// hoisted epilogue scale/bias loads.
__global__ void __launch_bounds__(NTHREADS, 1)
gemm_hmma_kernel(const float* __restrict__ wscale,
                 const float* __restrict__ bias,
                 float* __restrict__ out)
{
    extern __shared__ char smem[];
    const uint32_t sb = smem_u32(smem);
    const int tid  = threadIdx.x;
    const int wid  = tid >> 5;
    const int lane = tid & 31;
    const int g    = wid >> 2;        // group 0/1
    const int w    = wid & 3;
    const int wm   = w & 1;
    const int wn   = w >> 1;
    const int gtid = tid & 127;
    const int bid  = blockIdx.x;

    const int ntiles = (NTILES - 1 - bid) / GRID + 1;
    const int GJ = ntiles * KIT;

    const int l7   = lane & 7;
    const int hi8  = (lane >> 3) & 1;
    const int hi16 = lane >> 4;

    const int arow_base = wm * 64 + hi8 * 8 + l7;
    const int akb_base  = hi16 * 16;
    const int brow_base = wn * 64 + hi16 * 8 + l7;
    const int bkb_base  = hi8 * 16;

    float d[4][8][4];
    #pragma unroll
    for (int i = 0; i < 4; i++)
        #pragma unroll
        for (int j = 0; j < 8; j++)
            #pragma unroll
            for (int c = 0; c < 4; c++) d[i][j][c] = 0.0f;

    // incremental coordinates of the tile being LOADED (j+2 stream)
    int lt  = bid;                  // tile index of next load
    int lkt = 0;                    // kt within that tile
    int ln0 = (lt & (NTILE_N - 1)) * BN;
    int lm0 = (lt >> 4) * BM;

    // prologue: loads for j=0,1 (tile bid, kt 0 and 1)
    load_stage(sb, 0, lm0, ln0, 0, g, gtid);
    asm volatile("cp.async.commit_group;" ::: "memory");
    load_stage(sb, 1, lm0, ln0, 1, g, gtid);
    asm volatile("cp.async.commit_group;" ::: "memory");
    lkt = 2;

    // incremental coordinates of the tile being COMPUTED / epilogued
    int et  = bid;
    int en0 = ln0, em0 = lm0;

    int s0 = 0;   // stage of j
    int s2 = 2;   // stage of j+2

    #pragma unroll 1
    for (int j = 0; j < GJ; j++) {
        if (j + 2 < GJ)
            asm volatile("cp.async.wait_group 1;" ::: "memory");
        else
            asm volatile("cp.async.wait_group 0;" ::: "memory");
        group_bar(g);   // stage j resident for this group

        if (j + 2 < GJ) {
            load_stage(sb, s2, lm0, ln0, lkt, g, gtid);
            asm volatile("cp.async.commit_group;" ::: "memory");
            if (++lkt == KIT) {
                lkt = 0;
                lt += GRID;
                ln0 = (lt & (NTILE_N - 1)) * BN;
                lm0 = (lt >> 4) * BM;
            }
        }

        const uint32_t abase = sb + (uint32_t)s0 * STAGE_BYTES + (uint32_t)g * GROUP_BYTES;
        const uint32_t bbase = abase + GROUP_A_BYTES;

        #pragma unroll
        for (int ks = 0; ks < BK / 16; ks++) {
            uint32_t a[4][4];
            #pragma unroll
            for (int mt = 0; mt < 4; mt++) {
                uint32_t off = (uint32_t)(arow_base + mt * 16) * 128
                             + (uint32_t)(ks * 32 + akb_base);
                ldm_x4(abase + sw128(off), a[mt][0], a[mt][1], a[mt][2], a[mt][3]);
            }
            uint32_t bfr[8][2];
            #pragma unroll
            for (int np = 0; np < 4; np++) {
                uint32_t off = (uint32_t)(brow_base + np * 16) * 128
                             + (uint32_t)(ks * 32 + bkb_base);
                uint32_t r0, r1, r2, r3;
                ldm_x4(bbase + sw128(off), r0, r1, r2, r3);
                bfr[np * 2 + 0][0] = r0; bfr[np * 2 + 0][1] = r1;
                bfr[np * 2 + 1][0] = r2; bfr[np * 2 + 1][1] = r3;
            }
            #pragma unroll
            for (int mt = 0; mt < 4; mt++)
                #pragma unroll
                for (int nt = 0; nt < 8; nt++)
                    mma16816(d[mt][nt][0], d[mt][nt][1], d[mt][nt][2], d[mt][nt][3],
                             a[mt][0], a[mt][1], a[mt][2], a[mt][3],
                             bfr[nt][0], bfr[nt][1]);
        }

        s0 = (s0 == 2) ? 0 : s0 + 1;
        s2 = (s2 == 2) ? 0 : s2 + 1;

        // ---------------- tile epilogue ----------------
        if ((j & (KIT - 1)) == KIT - 1) {
            const int crow = em0 + wm * 64 + (lane >> 2);
            const int ccol = en0 + g * 128 + wn * 64 + (lane & 3) * 2;

            float sc0[8], sc1[8], bi0[8], bi1[8];
            #pragma unroll
            for (int nt = 0; nt < 8; nt++) {
                sc0[nt] = __ldg(wscale + ccol + nt * 8);
                sc1[nt] = __ldg(wscale + ccol + nt * 8 + 1);
                bi0[nt] = __ldg(bias   + ccol + nt * 8);
                bi1[nt] = __ldg(bias   + ccol + nt * 8 + 1);
            }

            #pragma unroll
            for (int mt = 0; mt < 4; mt++) {
                #pragma unroll
                for (int nt = 0; nt < 8; nt++) {
                    float2 v0, v1;
                    v0.x = fmaf(d[mt][nt][0], sc0[nt], bi0[nt]);
                    v0.y = fmaf(d[mt][nt][1], sc1[nt], bi1[nt]);
                    v1.x = fmaf(d[mt][nt][2], sc0[nt], bi0[nt]);
                    v1.y = fmaf(d[mt][nt][3], sc1[nt], bi1[nt]);
                    size_t r0 = (size_t)(crow + mt * 16) * SZ_N + ccol + nt * 8;
                    size_t r1 = r0 + 8 * SZ_N;
                    *reinterpret_cast<float2*>(out + r0) = v0;
                    *reinterpret_cast<float2*>(out + r1) = v1;
                    d[mt][nt][0] = 0.0f; d[mt][nt][1] = 0.0f;
                    d[mt][nt][2] = 0.0f; d[mt][nt][3] = 0.0f;
                }
            }

            et += GRID;
            en0 = (et & (NTILE_N - 1)) * BN;
            em0 = (et >> 4) * BM;
        }
    }
}

// ---------------- launch ----------------
extern "C" void kernel_launch(void* const* d_in, const int* in_sizes, int n_in,
                              void* d_out, int out_size)
{
    const float* x  = (const float*)d_in[0];   // [4,2048,4096] fp32
    const int*   qw = (const int*)  d_in[1];   // [4096,4096] int32 in [-8,7]
    const float* ws = (const float*)d_in[2];   // [4096]
    const float* bs = (const float*)d_in[3];   // [4096]
    float* out = (float*)d_out;                // [4,2048,4096] fp32

    cudaFuncSetAttribute(gemm_hmma_kernel,
                         cudaFuncAttributeMaxDynamicSharedMemorySize, SMEM_TOTAL);

    cvt_all_kernel<<<(unsigned)((XC + WC) / 256), 256>>>(x, qw);

    gemm_hmma_kernel<<<GRID, NTHREADS, SMEM_TOTAL>>>(ws, bs, out);
}